// round 1
// baseline (speedup 1.0000x reference)
#include <cuda_runtime.h>

// Problem constants
#define DD    256
#define HW    4096
#define NBAT  16
#define NTOK  65536          // NBAT * HW
#define KCB   2048
#define QSIZE 16777216       // NBAT * DD * HW
// out layout (float32): [0..QSIZE) q, [QSIZE] loss, [QSIZE+1] codebook_loss,
// [QSIZE+2] commitment_loss, [QSIZE+3 .. QSIZE+3+KCB) counts

__device__ float g_c2[KCB];
__device__ float g_z2[NTOK];

// ---------------------------------------------------------------------------
__global__ void init_out_kernel(float* out) {
    int i = threadIdx.x + blockIdx.x * blockDim.x;
    if (i < 3 + KCB) out[QSIZE + i] = 0.0f;
}

// c2[k] = sum_d codebook[k][d]^2  (one warp per code)
__global__ void c2_kernel(const float* __restrict__ cb) {
    int warp = (threadIdx.x >> 5) + blockIdx.x * (blockDim.x >> 5);
    int lane = threadIdx.x & 31;
    if (warp >= KCB) return;
    const float* row = cb + (size_t)warp * DD;
    float s = 0.f;
    #pragma unroll
    for (int d = lane; d < DD; d += 32) { float v = row[d]; s = fmaf(v, v, s); }
    #pragma unroll
    for (int off = 16; off; off >>= 1) s += __shfl_down_sync(0xffffffffu, s, off);
    if (lane == 0) g_c2[warp] = s;
}

// z2[n] = sum_d z_flat[n][d]^2  (sequential fp32 sum, coalesced across tokens)
__global__ void z2_kernel(const float* __restrict__ z) {
    int n = threadIdx.x + blockIdx.x * blockDim.x;
    if (n >= NTOK) return;
    int b = n >> 12, hw = n & 4095;
    const float* p = z + (size_t)b * (DD * HW) + hw;
    float s = 0.f;
    #pragma unroll 8
    for (int d = 0; d < DD; d++) { float v = p[(size_t)d * HW]; s = fmaf(v, v, s); }
    g_z2[n] = s;
}

// ---------------------------------------------------------------------------
// Main kernel: per block, 128 tokens x (all 2048 codes) fused GEMM + argmin,
// then counts / q / loss epilogue.
__global__ __launch_bounds__(256, 2)
void vq_main_kernel(const float* __restrict__ z, const float* __restrict__ cb,
                    float* __restrict__ out) {
    __shared__ float As[8][128];            // [d][token]
    __shared__ float Bs[8][132];            // [d][code], padded
    __shared__ unsigned long long red[128][16];
    __shared__ int   idx_s[128];
    __shared__ float z2_s[128];
    __shared__ float lred[8];

    const int tid = threadIdx.x;
    const int tx = tid & 15;                // code micro-dim
    const int ty = tid >> 4;                // token micro-dim
    const int n0 = blockIdx.x * 128;
    const int b  = n0 >> 12;                // 128 | 4096 -> one batch per block
    const int hw0 = n0 & 4095;
    const float* zbase = z + (size_t)b * (DD * HW) + hw0;

    if (tid < 128) z2_s[tid] = g_z2[n0 + tid];

    unsigned long long minkey[8];
    #pragma unroll
    for (int i = 0; i < 8; i++) minkey[i] = ~0ULL;

    const int a_dd = tid >> 5;              // A-tile load coords
    const int a_tq = (tid & 31) * 4;
    const int b_kk = tid >> 1;              // B-tile load coords
    const int b_p  = (tid & 1) * 4;

    for (int kc = 0; kc < KCB; kc += 128) {
        float acc[8][8];
        #pragma unroll
        for (int i = 0; i < 8; i++)
            #pragma unroll
            for (int j = 0; j < 8; j++) acc[i][j] = 0.f;

        for (int dc = 0; dc < DD; dc += 8) {
            float4 av = *(const float4*)(zbase + (size_t)(dc + a_dd) * HW + a_tq);
            float4 bv = *(const float4*)(cb + (size_t)(kc + b_kk) * DD + dc + b_p);
            __syncthreads();
            *(float4*)&As[a_dd][a_tq] = av;
            Bs[b_p + 0][b_kk] = bv.x;
            Bs[b_p + 1][b_kk] = bv.y;
            Bs[b_p + 2][b_kk] = bv.z;
            Bs[b_p + 3][b_kk] = bv.w;
            __syncthreads();

            #pragma unroll
            for (int d2 = 0; d2 < 8; d2++) {
                float a[8], bb[8];
                #pragma unroll
                for (int i = 0; i < 8; i++) a[i] = As[d2][ty + 16 * i];
                #pragma unroll
                for (int j = 0; j < 8; j++) bb[j] = Bs[d2][tx + 16 * j];
                #pragma unroll
                for (int i = 0; i < 8; i++)
                    #pragma unroll
                    for (int j = 0; j < 8; j++)
                        acc[i][j] = fmaf(a[i], bb[j], acc[i][j]);
            }
        }

        // score epilogue for this 128-code chunk (replicates reference rounding:
        // dist = fl( fl(z2 + c2) - 2*dot ), first-index tie-break)
        #pragma unroll
        for (int j = 0; j < 8; j++) {
            int k = kc + tx + 16 * j;
            float c2k = g_c2[k];
            #pragma unroll
            for (int i = 0; i < 8; i++) {
                int tok = ty + 16 * i;
                float t1 = z2_s[tok] + c2k;
                float dist = fmaf(-2.0f, acc[i][j], t1);
                unsigned int ub = __float_as_uint(dist);
                ub = (ub & 0x80000000u) ? ~ub : (ub | 0x80000000u);
                unsigned long long key = ((unsigned long long)ub << 32) | (unsigned)k;
                if (key < minkey[i]) minkey[i] = key;
            }
        }
    }

    // cross-thread argmin reduction (per token)
    #pragma unroll
    for (int i = 0; i < 8; i++) red[ty + 16 * i][tx] = minkey[i];
    __syncthreads();
    if (tid < 128) {
        unsigned long long m = red[tid][0];
        #pragma unroll
        for (int t = 1; t < 16; t++) {
            unsigned long long v = red[tid][t];
            if (v < m) m = v;
        }
        int k = (int)(m & 0xFFFFFFFFu);
        idx_s[tid] = k;
        atomicAdd(out + QSIZE + 3 + k, 1.0f);   // counts (exact integer fp32)
    }
    __syncthreads();

    // q write (straight-through, replicating fp32 expression z + (zq - z))
    // + fused MSE partial sum
    const int tok = tid & 127;
    const int half = tid >> 7;
    const int kidx = idx_s[tok];
    const float* crow = cb + (size_t)kidx * DD;
    float* qbase = out + (size_t)b * (DD * HW) + hw0 + tok;
    const float* zb2 = zbase + tok;
    float lsum = 0.f;
    #pragma unroll 4
    for (int d = half * 128; d < half * 128 + 128; d++) {
        float c  = crow[d];
        float zz = zb2[(size_t)d * HW];
        float df = zz - c;
        lsum = fmaf(df, df, lsum);
        qbase[(size_t)d * HW] = zz + (c - zz);   // == reference ST rounding
    }
    #pragma unroll
    for (int off = 16; off; off >>= 1) lsum += __shfl_down_sync(0xffffffffu, lsum, off);
    if ((tid & 31) == 0) lred[tid >> 5] = lsum;
    __syncthreads();
    if (tid == 0) {
        float s = 0.f;
        #pragma unroll
        for (int w = 0; w < 8; w++) s += lred[w];
        atomicAdd(out + QSIZE + 1, s);           // raw SSE accumulator
    }
}

// ---------------------------------------------------------------------------
__global__ void finalize_kernel(float* out) {
    float sse = out[QSIZE + 1];
    float mse = sse / (float)((size_t)NTOK * DD);
    out[QSIZE]     = fmaf(0.25f, mse, mse);      // loss = 1.25 * mse
    out[QSIZE + 1] = mse;                        // codebook_loss
    out[QSIZE + 2] = mse;                        // commitment_loss
}

// ---------------------------------------------------------------------------
extern "C" void kernel_launch(void* const* d_in, const int* in_sizes, int n_in,
                              void* d_out, int out_size) {
    const float* z  = (const float*)d_in[0];     // (16, 256, 64, 64)
    const float* cb = (const float*)d_in[1];     // (2048, 256)
    float* out = (float*)d_out;

    init_out_kernel<<<9, 256>>>(out);
    c2_kernel<<<KCB / 8, 256>>>(cb);             // 8 warps/block, 1 code/warp
    z2_kernel<<<NTOK / 256, 256>>>(z);
    vq_main_kernel<<<NTOK / 128, 256>>>(z, cb, out);
    finalize_kernel<<<1, 1>>>(out);
}

// round 2
// speedup vs baseline: 1.0695x; 1.0695x over previous
#include <cuda_runtime.h>

// Problem constants
#define DD    256
#define HW    4096
#define NBAT  16
#define NTOK  65536          // NBAT * HW
#define KCB   2048
#define QSIZE 16777216       // NBAT * DD * HW
// out layout (float32): [0..QSIZE) q, [QSIZE] loss, [QSIZE+1] codebook_loss,
// [QSIZE+2] commitment_loss, [QSIZE+3 .. QSIZE+3+KCB) counts

__device__ float g_c2[KCB];
__device__ float g_z2[NTOK];

// ---------------------------------------------------------------------------
__device__ __forceinline__ unsigned long long dup2(float x) {
    unsigned long long r;
    asm("mov.b64 %0, {%1, %1};" : "=l"(r) : "f"(x));
    return r;
}
__device__ __forceinline__ void unpack2(unsigned long long v, float& lo, float& hi) {
    asm("mov.b64 {%0, %1}, %2;" : "=f"(lo), "=f"(hi) : "l"(v));
}
__device__ __forceinline__ void ffma2(unsigned long long& acc,
                                      unsigned long long a, unsigned long long b) {
    asm("fma.rn.f32x2 %0, %1, %2, %0;" : "+l"(acc) : "l"(a), "l"(b));
}

// ---------------------------------------------------------------------------
__global__ void init_out_kernel(float* out) {
    int i = threadIdx.x + blockIdx.x * blockDim.x;
    if (i < 3 + KCB) out[QSIZE + i] = 0.0f;
}

// c2[k] = sum_d codebook[k][d]^2  (one warp per code)
__global__ void c2_kernel(const float* __restrict__ cb) {
    int warp = (threadIdx.x >> 5) + blockIdx.x * (blockDim.x >> 5);
    int lane = threadIdx.x & 31;
    if (warp >= KCB) return;
    const float* row = cb + (size_t)warp * DD;
    float s = 0.f;
    #pragma unroll
    for (int d = lane; d < DD; d += 32) { float v = row[d]; s = fmaf(v, v, s); }
    #pragma unroll
    for (int off = 16; off; off >>= 1) s += __shfl_down_sync(0xffffffffu, s, off);
    if (lane == 0) g_c2[warp] = s;
}

// z2[n] = sum_d z_flat[n][d]^2  (sequential fp32 sum, coalesced across tokens)
__global__ void z2_kernel(const float* __restrict__ z) {
    int n = threadIdx.x + blockIdx.x * blockDim.x;
    if (n >= NTOK) return;
    int b = n >> 12, hw = n & 4095;
    const float* p = z + (size_t)b * (DD * HW) + hw;
    float s = 0.f;
    #pragma unroll 8
    for (int d = 0; d < DD; d++) { float v = p[(size_t)d * HW]; s = fmaf(v, v, s); }
    g_z2[n] = s;
}

// ---------------------------------------------------------------------------
// Main kernel: per block, 128 tokens x 2048 codes fused GEMM + argmin with
// packed fp32x2 FMAs (SASS FFMA2). Token operand staged duplicated in smem;
// code operand packed as adjacent pairs.
__global__ __launch_bounds__(256, 2)
void vq_main_kernel(const float* __restrict__ z, const float* __restrict__ cb,
                    float* __restrict__ out) {
    __shared__ unsigned long long As2[8][128];   // [d][token] duplicated (z,z)
    __shared__ __align__(16) float Bs[8][132];   // [d][code], pad 132 (even, 8B ok)
    __shared__ unsigned long long red[128][16];
    __shared__ int   idx_s[128];
    __shared__ float z2_s[128];
    __shared__ float lred[8];

    const int tid = threadIdx.x;
    const int tx = tid & 15;                // code-pair micro-dim
    const int ty = tid >> 4;                // token micro-dim
    const int n0 = blockIdx.x * 128;
    const int b  = n0 >> 12;                // 128 | 4096 -> one batch per block
    const int hw0 = n0 & 4095;
    const float* zbase = z + (size_t)b * (DD * HW) + hw0;

    if (tid < 128) z2_s[tid] = g_z2[n0 + tid];

    float best[8];
    int   bestk[8];
    #pragma unroll
    for (int i = 0; i < 8; i++) { best[i] = __int_as_float(0x7f800000); bestk[i] = 0; }

    const int a_dd = tid >> 5;              // A-tile load coords
    const int a_tq = (tid & 31) * 4;
    const int b_kk = tid >> 1;              // B-tile load coords
    const int b_p  = (tid & 1) * 4;

    for (int kc = 0; kc < KCB; kc += 128) {
        unsigned long long acc[8][4];       // [token i][code pair j2]
        #pragma unroll
        for (int i = 0; i < 8; i++)
            #pragma unroll
            for (int j = 0; j < 4; j++) acc[i][j] = 0ULL;

        for (int dc = 0; dc < DD; dc += 8) {
            float4 av = *(const float4*)(zbase + (size_t)(dc + a_dd) * HW + a_tq);
            float4 bv = *(const float4*)(cb + (size_t)(kc + b_kk) * DD + dc + b_p);
            __syncthreads();
            As2[a_dd][a_tq + 0] = dup2(av.x);
            As2[a_dd][a_tq + 1] = dup2(av.y);
            As2[a_dd][a_tq + 2] = dup2(av.z);
            As2[a_dd][a_tq + 3] = dup2(av.w);
            Bs[b_p + 0][b_kk] = bv.x;
            Bs[b_p + 1][b_kk] = bv.y;
            Bs[b_p + 2][b_kk] = bv.z;
            Bs[b_p + 3][b_kk] = bv.w;
            __syncthreads();

            #pragma unroll
            for (int d2 = 0; d2 < 8; d2++) {
                unsigned long long a2[8], b2[4];
                #pragma unroll
                for (int i = 0; i < 8; i++) a2[i] = As2[d2][ty + 16 * i];
                #pragma unroll
                for (int j = 0; j < 4; j++)
                    b2[j] = *(const unsigned long long*)&Bs[d2][tx * 2 + 32 * j];
                #pragma unroll
                for (int i = 0; i < 8; i++)
                    #pragma unroll
                    for (int j = 0; j < 4; j++)
                        ffma2(acc[i][j], a2[i], b2[j]);
            }
        }

        // score epilogue (replicates reference rounding:
        // dist = fl( fl(z2 + c2) - 2*dot ); strict-< in increasing-k order
        // per thread => first-index tie-break within thread)
        #pragma unroll
        for (int j = 0; j < 4; j++) {
            int k0 = kc + tx * 2 + 32 * j;
            float c20 = g_c2[k0];
            float c21 = g_c2[k0 + 1];
            #pragma unroll
            for (int i = 0; i < 8; i++) {
                float dot0, dot1;
                unpack2(acc[i][j], dot0, dot1);
                float zz = z2_s[ty + 16 * i];
                float dist0 = fmaf(-2.0f, dot0, zz + c20);
                float dist1 = fmaf(-2.0f, dot1, zz + c21);
                if (dist0 < best[i]) { best[i] = dist0; bestk[i] = k0; }
                if (dist1 < best[i]) { best[i] = dist1; bestk[i] = k0 + 1; }
            }
        }
    }

    // cross-thread argmin reduction (per token); dist > 0 so raw float bits
    // are order-monotone; (bits<<32)|k gives smallest-k tie-break
    #pragma unroll
    for (int i = 0; i < 8; i++) {
        unsigned long long key =
            ((unsigned long long)__float_as_uint(best[i]) << 32) | (unsigned)bestk[i];
        red[ty + 16 * i][tx] = key;
    }
    __syncthreads();
    if (tid < 128) {
        unsigned long long m = red[tid][0];
        #pragma unroll
        for (int t = 1; t < 16; t++) {
            unsigned long long v = red[tid][t];
            if (v < m) m = v;
        }
        int k = (int)(m & 0xFFFFFFFFu);
        idx_s[tid] = k;
        atomicAdd(out + QSIZE + 3 + k, 1.0f);   // counts (exact integer fp32)
    }
    __syncthreads();

    // q write (straight-through, replicating fp32 expression z + (zq - z))
    // + fused MSE partial sum
    const int tok = tid & 127;
    const int half = tid >> 7;
    const int kidx = idx_s[tok];
    const float* crow = cb + (size_t)kidx * DD;
    float* qbase = out + (size_t)b * (DD * HW) + hw0 + tok;
    const float* zb2 = zbase + tok;
    float lsum = 0.f;
    #pragma unroll 4
    for (int d = half * 128; d < half * 128 + 128; d++) {
        float c  = crow[d];
        float zz = zb2[(size_t)d * HW];
        float df = zz - c;
        lsum = fmaf(df, df, lsum);
        qbase[(size_t)d * HW] = zz + (c - zz);   // == reference ST rounding
    }
    #pragma unroll
    for (int off = 16; off; off >>= 1) lsum += __shfl_down_sync(0xffffffffu, lsum, off);
    if ((tid & 31) == 0) lred[tid >> 5] = lsum;
    __syncthreads();
    if (tid == 0) {
        float s = 0.f;
        #pragma unroll
        for (int w = 0; w < 8; w++) s += lred[w];
        atomicAdd(out + QSIZE + 1, s);           // raw SSE accumulator
    }
}

// ---------------------------------------------------------------------------
__global__ void finalize_kernel(float* out) {
    float sse = out[QSIZE + 1];
    float mse = sse / (float)((size_t)NTOK * DD);
    out[QSIZE]     = fmaf(0.25f, mse, mse);      // loss = 1.25 * mse
    out[QSIZE + 1] = mse;                        // codebook_loss
    out[QSIZE + 2] = mse;                        // commitment_loss
}

// ---------------------------------------------------------------------------
extern "C" void kernel_launch(void* const* d_in, const int* in_sizes, int n_in,
                              void* d_out, int out_size) {
    const float* z  = (const float*)d_in[0];     // (16, 256, 64, 64)
    const float* cb = (const float*)d_in[1];     // (2048, 256)
    float* out = (float*)d_out;

    init_out_kernel<<<9, 256>>>(out);
    c2_kernel<<<KCB / 8, 256>>>(cb);             // 8 warps/block, 1 code/warp
    z2_kernel<<<NTOK / 256, 256>>>(z);
    vq_main_kernel<<<NTOK / 128, 256>>>(z, cb, out);
    finalize_kernel<<<1, 1>>>(out);
}

// round 3
// speedup vs baseline: 1.0713x; 1.0017x over previous
#include <cuda_runtime.h>

// Problem constants
#define DD    256
#define HW    4096
#define NBAT  16
#define NTOK  65536          // NBAT * HW
#define KCB   2048
#define QSIZE 16777216       // NBAT * DD * HW
// out layout (float32): [0..QSIZE) q, [QSIZE] loss, [QSIZE+1] codebook_loss,
// [QSIZE+2] commitment_loss, [QSIZE+3 .. QSIZE+3+KCB) counts

__device__ float g_c2[KCB];
__device__ float g_z2[NTOK];

// ---------------------------------------------------------------------------
__device__ __forceinline__ unsigned long long dup2(float x) {
    unsigned long long r;
    asm("mov.b64 %0, {%1, %1};" : "=l"(r) : "f"(x));
    return r;
}
__device__ __forceinline__ void unpack2(unsigned long long v, float& lo, float& hi) {
    asm("mov.b64 {%0, %1}, %2;" : "=f"(lo), "=f"(hi) : "l"(v));
}
__device__ __forceinline__ void ffma2(unsigned long long& acc,
                                      unsigned long long a, unsigned long long b) {
    asm("fma.rn.f32x2 %0, %1, %2, %0;" : "+l"(acc) : "l"(a), "l"(b));
}

// ---------------------------------------------------------------------------
__global__ void init_out_kernel(float* out) {
    int i = threadIdx.x + blockIdx.x * blockDim.x;
    if (i < 3 + KCB) out[QSIZE + i] = 0.0f;
}

// c2[k] = sum_d codebook[k][d]^2  (one warp per code)
__global__ void c2_kernel(const float* __restrict__ cb) {
    int warp = (threadIdx.x >> 5) + blockIdx.x * (blockDim.x >> 5);
    int lane = threadIdx.x & 31;
    if (warp >= KCB) return;
    const float* row = cb + (size_t)warp * DD;
    float s = 0.f;
    #pragma unroll
    for (int d = lane; d < DD; d += 32) { float v = row[d]; s = fmaf(v, v, s); }
    #pragma unroll
    for (int off = 16; off; off >>= 1) s += __shfl_down_sync(0xffffffffu, s, off);
    if (lane == 0) g_c2[warp] = s;
}

// z2[n] = sum_d z_flat[n][d]^2  (sequential fp32 sum, coalesced across tokens)
__global__ void z2_kernel(const float* __restrict__ z) {
    int n = threadIdx.x + blockIdx.x * blockDim.x;
    if (n >= NTOK) return;
    int b = n >> 12, hw = n & 4095;
    const float* p = z + (size_t)b * (DD * HW) + hw;
    float s = 0.f;
    #pragma unroll 8
    for (int d = 0; d < DD; d++) { float v = p[(size_t)d * HW]; s = fmaf(v, v, s); }
    g_z2[n] = s;
}

// ---------------------------------------------------------------------------
// Main kernel: per block, 128 tokens x 2048 codes fused GEMM + argmin with
// packed fp32x2 FMAs (SASS FFMA2). Token operand staged duplicated in smem;
// code operand packed as adjacent pairs.
__global__ __launch_bounds__(256, 2)
void vq_main_kernel(const float* __restrict__ z, const float* __restrict__ cb,
                    float* __restrict__ out) {
    __shared__ unsigned long long As2[8][128];   // [d][token] duplicated (z,z)
    __shared__ __align__(16) float Bs[8][132];   // [d][code], pad 132 (even, 8B ok)
    __shared__ unsigned long long red[128][16];
    __shared__ int   idx_s[128];
    __shared__ float z2_s[128];
    __shared__ float lred[8];

    const int tid = threadIdx.x;
    const int tx = tid & 15;                // code-pair micro-dim
    const int ty = tid >> 4;                // token micro-dim
    const int n0 = blockIdx.x * 128;
    const int b  = n0 >> 12;                // 128 | 4096 -> one batch per block
    const int hw0 = n0 & 4095;
    const float* zbase = z + (size_t)b * (DD * HW) + hw0;

    if (tid < 128) z2_s[tid] = g_z2[n0 + tid];

    float best[8];
    int   bestk[8];
    #pragma unroll
    for (int i = 0; i < 8; i++) { best[i] = __int_as_float(0x7f800000); bestk[i] = 0; }

    const int a_dd = tid >> 5;              // A-tile load coords
    const int a_tq = (tid & 31) * 4;
    const int b_kk = tid >> 1;              // B-tile load coords
    const int b_p  = (tid & 1) * 4;

    for (int kc = 0; kc < KCB; kc += 128) {
        unsigned long long acc[8][4];       // [token i][code pair j2]
        #pragma unroll
        for (int i = 0; i < 8; i++)
            #pragma unroll
            for (int j = 0; j < 4; j++) acc[i][j] = 0ULL;

        for (int dc = 0; dc < DD; dc += 8) {
            float4 av = *(const float4*)(zbase + (size_t)(dc + a_dd) * HW + a_tq);
            float4 bv = *(const float4*)(cb + (size_t)(kc + b_kk) * DD + dc + b_p);
            __syncthreads();
            As2[a_dd][a_tq + 0] = dup2(av.x);
            As2[a_dd][a_tq + 1] = dup2(av.y);
            As2[a_dd][a_tq + 2] = dup2(av.z);
            As2[a_dd][a_tq + 3] = dup2(av.w);
            Bs[b_p + 0][b_kk] = bv.x;
            Bs[b_p + 1][b_kk] = bv.y;
            Bs[b_p + 2][b_kk] = bv.z;
            Bs[b_p + 3][b_kk] = bv.w;
            __syncthreads();

            #pragma unroll
            for (int d2 = 0; d2 < 8; d2++) {
                unsigned long long a2[8], b2[4];
                #pragma unroll
                for (int i = 0; i < 8; i++) a2[i] = As2[d2][ty + 16 * i];
                #pragma unroll
                for (int j = 0; j < 4; j++)
                    b2[j] = *(const unsigned long long*)&Bs[d2][tx * 2 + 32 * j];
                #pragma unroll
                for (int i = 0; i < 8; i++)
                    #pragma unroll
                    for (int j = 0; j < 4; j++)
                        ffma2(acc[i][j], a2[i], b2[j]);
            }
        }

        // score epilogue (replicates reference rounding:
        // dist = fl( fl(z2 + c2) - 2*dot ); strict-< in increasing-k order
        // per thread => first-index tie-break within thread)
        #pragma unroll
        for (int j = 0; j < 4; j++) {
            int k0 = kc + tx * 2 + 32 * j;
            float c20 = g_c2[k0];
            float c21 = g_c2[k0 + 1];
            #pragma unroll
            for (int i = 0; i < 8; i++) {
                float dot0, dot1;
                unpack2(acc[i][j], dot0, dot1);
                float zz = z2_s[ty + 16 * i];
                float dist0 = fmaf(-2.0f, dot0, zz + c20);
                float dist1 = fmaf(-2.0f, dot1, zz + c21);
                if (dist0 < best[i]) { best[i] = dist0; bestk[i] = k0; }
                if (dist1 < best[i]) { best[i] = dist1; bestk[i] = k0 + 1; }
            }
        }
    }

    // cross-thread argmin reduction (per token); dist > 0 so raw float bits
    // are order-monotone; (bits<<32)|k gives smallest-k tie-break
    #pragma unroll
    for (int i = 0; i < 8; i++) {
        unsigned long long key =
            ((unsigned long long)__float_as_uint(best[i]) << 32) | (unsigned)bestk[i];
        red[ty + 16 * i][tx] = key;
    }
    __syncthreads();
    if (tid < 128) {
        unsigned long long m = red[tid][0];
        #pragma unroll
        for (int t = 1; t < 16; t++) {
            unsigned long long v = red[tid][t];
            if (v < m) m = v;
        }
        int k = (int)(m & 0xFFFFFFFFu);
        idx_s[tid] = k;
        atomicAdd(out + QSIZE + 3 + k, 1.0f);   // counts (exact integer fp32)
    }
    __syncthreads();

    // q write (straight-through, replicating fp32 expression z + (zq - z))
    // + fused MSE partial sum
    const int tok = tid & 127;
    const int half = tid >> 7;
    const int kidx = idx_s[tok];
    const float* crow = cb + (size_t)kidx * DD;
    float* qbase = out + (size_t)b * (DD * HW) + hw0 + tok;
    const float* zb2 = zbase + tok;
    float lsum = 0.f;
    #pragma unroll 4
    for (int d = half * 128; d < half * 128 + 128; d++) {
        float c  = crow[d];
        float zz = zb2[(size_t)d * HW];
        float df = zz - c;
        lsum = fmaf(df, df, lsum);
        qbase[(size_t)d * HW] = zz + (c - zz);   // == reference ST rounding
    }
    #pragma unroll
    for (int off = 16; off; off >>= 1) lsum += __shfl_down_sync(0xffffffffu, lsum, off);
    if ((tid & 31) == 0) lred[tid >> 5] = lsum;
    __syncthreads();
    if (tid == 0) {
        float s = 0.f;
        #pragma unroll
        for (int w = 0; w < 8; w++) s += lred[w];
        atomicAdd(out + QSIZE + 1, s);           // raw SSE accumulator
    }
}

// ---------------------------------------------------------------------------
__global__ void finalize_kernel(float* out) {
    float sse = out[QSIZE + 1];
    float mse = sse / (float)((size_t)NTOK * DD);
    out[QSIZE]     = fmaf(0.25f, mse, mse);      // loss = 1.25 * mse
    out[QSIZE + 1] = mse;                        // codebook_loss
    out[QSIZE + 2] = mse;                        // commitment_loss
}

// ---------------------------------------------------------------------------
extern "C" void kernel_launch(void* const* d_in, const int* in_sizes, int n_in,
                              void* d_out, int out_size) {
    const float* z  = (const float*)d_in[0];     // (16, 256, 64, 64)
    const float* cb = (const float*)d_in[1];     // (2048, 256)
    float* out = (float*)d_out;

    init_out_kernel<<<9, 256>>>(out);
    c2_kernel<<<KCB / 8, 256>>>(cb);             // 8 warps/block, 1 code/warp
    z2_kernel<<<NTOK / 256, 256>>>(z);
    vq_main_kernel<<<NTOK / 128, 256>>>(z, cb, out);
    finalize_kernel<<<1, 1>>>(out);
}